// round 16
// baseline (speedup 1.0000x reference)
#include <cuda_runtime.h>
#include <cuda_bf16.h>
#include <math.h>
#include <cstdint>

#define L 2048
#define DIM 1024
#define NL 12
#define EX 2048
#define NS 16
#define DTRR 64
#define KC 4
#define VOCAB 50257
#define CHUNK 64
#define NCH 32
#define XPN 96
#define XPS 16         // split-K factor for x_proj
#define OPS 2          // split-K factor for out_proj

typedef __nv_bfloat16 bf;

__device__ __forceinline__ float silu_f(float x){ return x/(1.f+__expf(-x)); }
__device__ __forceinline__ float softplus_f(float x){ return fmaxf(x,0.f)+log1pf(__expf(-fabsf(x))); }

__device__ __forceinline__ void split1(float v, bf* hi, bf* lo){
    bf h = __float2bfloat16_rn(v);
    *hi = h;
    *lo = __float2bfloat16_rn(v - __bfloat162float(h));
}

__device__ __forceinline__ uint32_t smem_to_u32(const void* p){
    uint32_t a; asm("{ .reg .u64 t; cvta.to.shared.u64 t, %1; cvt.u32.u64 %0, t; }" : "=r"(a) : "l"(p));
    return a;
}
__device__ __forceinline__ void cp16(uint32_t dst, const void* src, int sz){
    asm volatile("cp.async.cg.shared.global [%0], [%1], 16, %2;" :: "r"(dst), "l"(src), "r"(sz));
}
#define CP_COMMIT() asm volatile("cp.async.commit_group;" ::: "memory")
#define CP_WAIT1()  asm volatile("cp.async.wait_group 1;" ::: "memory")

#define LDSM4(R, addr) \
  asm volatile("ldmatrix.sync.aligned.m8n8.x4.shared.b16 {%0,%1,%2,%3}, [%4];" \
    : "=r"((R)[0]),"=r"((R)[1]),"=r"((R)[2]),"=r"((R)[3]) : "r"(addr))

#define MMA(D, A, b0_, b1_) \
  asm volatile("mma.sync.aligned.m16n8k16.row.col.f32.bf16.bf16.f32 " \
    "{%0,%1,%2,%3}, {%4,%5,%6,%7}, {%8,%9}, {%0,%1,%2,%3};" \
    : "+f"((D)[0]),"+f"((D)[1]),"+f"((D)[2]),"+f"((D)[3]) \
    : "r"((A)[0]),"r"((A)[1]),"r"((A)[2]),"r"((A)[3]), "r"(b0_),"r"(b1_))

// ===================== scratch (static device memory) =====================
#define SZ_MAT (L*DIM)
#define SZ_XZ  (L*2*EX)
#define SZ_E   (L*EX)
#define SZ_DBC (L*XPN)
#define SZ_PF  (NCH*EX*NS)

#define O_RES 0
#define O_XP  (O_RES+SZ_MAT)            // out_proj partials: OPS x L x DIM
#define O_XZ  (O_XP+OPS*SZ_MAT)
#define O_XC  (O_XZ+SZ_XZ)
#define O_DT  (O_XC+SZ_E)
#define O_DBC (O_DT+SZ_E)
#define O_P   (O_DBC+SZ_DBC)
#define O_F   (O_P+SZ_PF)
#define O_HIN (O_F+SZ_PF)
#define O_XPP (O_HIN+SZ_PF)
#define SCRATCH_TOTAL (O_XPP + XPS*SZ_DBC)

__device__ __align__(256) float g_scr[SCRATCH_TOTAL];

// pre-converted hi/lo weight buffers (whole model, converted once per launch)
#define N_INW  (NL*2*EX*DIM)
#define N_XPW  (NL*XPN*EX)
#define N_DTW  (NL*EX*DTRR)
#define N_OUTW (NL*DIM*EX)
#define N_HW   (VOCAB*DIM)
__device__ __align__(256) bf g_inwh[N_INW],  g_inwl[N_INW];
__device__ __align__(256) bf g_xpwh[N_XPW],  g_xpwl[N_XPW];
__device__ __align__(256) bf g_dtwh[N_DTW],  g_dtwl[N_DTW];
__device__ __align__(256) bf g_outwh[N_OUTW],g_outwl[N_OUTW];
__device__ __align__(256) bf g_hwh[N_HW],    g_hwl[N_HW];
// activation hi/lo buffers
__device__ __align__(256) bf g_hhi[L*DIM],  g_hlo[L*DIM];
__device__ __align__(256) bf g_xchi[L*EX],  g_xclo[L*EX];
__device__ __align__(256) bf g_dbch[L*XPN], g_dbcl[L*XPN];
__device__ __align__(256) bf g_yhi[L*EX],   g_ylo[L*EX];

// ===================== all-weights fp32 -> (hi,lo) split, one kernel =====================
#define C_INW  (N_INW/8)
#define C_XPW  (C_INW + N_XPW/8)
#define C_DTW  (C_XPW + N_DTW/8)
#define C_OUTW (C_DTW + N_OUTW/8)
#define C_HW   (C_OUTW + N_HW/8)

__device__ __forceinline__ void cvt8_one(const float* __restrict__ src, bf* hi, bf* lo, size_t i){
    const float4* s = (const float4*)src + 2*i;
    float4 a = s[0], b = s[1];
    float f[8] = {a.x,a.y,a.z,a.w,b.x,b.y,b.z,b.w};
    union { bf h[8]; uint4 u; } H; union { bf l[8]; uint4 u; } Lo;
#pragma unroll
    for (int j=0;j<8;j++) split1(f[j], &H.h[j], &Lo.l[j]);
    ((uint4*)hi)[i] = H.u;
    ((uint4*)lo)[i] = Lo.u;
}

__global__ void cvtall_k(const float* __restrict__ inw, const float* __restrict__ xpw,
                         const float* __restrict__ dtw, const float* __restrict__ outw,
                         const float* __restrict__ hw){
    size_t i = (size_t)blockIdx.x*256 + threadIdx.x;
    if (i < C_INW)       cvt8_one(inw,  g_inwh,  g_inwl,  i);
    else if (i < C_XPW)  cvt8_one(xpw,  g_xpwh,  g_xpwl,  i - C_INW);
    else if (i < C_DTW)  cvt8_one(dtw,  g_dtwh,  g_dtwl,  i - C_XPW);
    else if (i < C_OUTW) cvt8_one(outw, g_outwh, g_outwl, i - C_DTW);
    else if (i < C_HW)   cvt8_one(hw,   g_hwh,   g_hwl,   i - C_OUTW);
}

// ===================== mma.sync bf16x3 GEMM: C[M,N] = A[M,K] * B[N,K]^T =====================
// 128x128 CTA tile, BK=32, 3-stage cp.async pipeline, 8 warps (4m x 2n),
// warp tile 32x64. bf16x3: acc += Ah*Bh + Ah*Bl + Al*Bh, issued in 3 rounds
// of 4 independent MMAs each to break accumulator RAW chains.
#define STAGE_BYTES 32768
#define MM_SMEM (3*STAGE_BYTES)

__device__ __forceinline__ void ldgsts_stage(uint32_t sstage,
    const bf* __restrict__ Ahi, const bf* __restrict__ Alo, int lda,
    const bf* __restrict__ Bhi, const bf* __restrict__ Blo, int ldb,
    int bm, int bn, int N, int ktg, int tid)
{
#pragma unroll
    for (int j=0;j<2;j++){
        int ci = tid + j*256;
        int row = ci>>2, kc = ci&3;
        uint32_t dst = sstage + (uint32_t)(row*64 + ((kc ^ ((row>>1)&3))<<4));
        size_t aoff = (size_t)(bm+row)*lda + ktg + kc*8;
        cp16(dst,         Ahi + aoff, 16);
        cp16(dst + 8192,  Alo + aoff, 16);
        int brow = bn + row;
        int ok = (brow < N) ? 16 : 0;
        size_t boff = (size_t)(ok ? brow : bn)*ldb + ktg + kc*8;
        cp16(dst + 16384, Bhi + boff, ok);
        cp16(dst + 24576, Blo + boff, ok);
    }
}

template<int EPI>
__global__ __launch_bounds__(256,2)
void mm_gemm(const bf* __restrict__ Ahi, const bf* __restrict__ Alo, int lda,
             const bf* __restrict__ Bhi, const bf* __restrict__ Blo, int ldb,
             float* __restrict__ C, int ldc, int partStride, int N, int kLen,
             const float* __restrict__ bias)
{
    extern __shared__ char smem[];
    const uint32_t sb = smem_to_u32(smem);
    const int tid = threadIdx.x, lane = tid&31, wid = tid>>5;
    const int wm = wid&3, wn = wid>>2;
    const int bm = blockIdx.x*128, bn = blockIdx.y*128;
    const int k0 = blockIdx.z*kLen;
    const int ktiles = kLen/32;

    // prefetch stages 0,1 (ktiles >= 2 for all call sites)
    ldgsts_stage(sb,             Ahi,Alo,lda, Bhi,Blo,ldb, bm,bn,N, k0,    tid); CP_COMMIT();
    ldgsts_stage(sb+STAGE_BYTES, Ahi,Alo,lda, Bhi,Blo,ldb, bm,bn,N, k0+32, tid); CP_COMMIT();

    float acc[2][8][4];
#pragma unroll
    for (int a=0;a<2;a++)
#pragma unroll
        for (int b=0;b<8;b++)
#pragma unroll
            for (int c=0;c<4;c++) acc[a][b][c]=0.f;

    const int a_row_l = (lane&15);
    const int kc_l    = (lane>>4);

    for (int i=0;i<ktiles;i++){
        CP_WAIT1();
        __syncthreads();
        if (i+2 < ktiles)
            ldgsts_stage(sb + ((i+2)%3)*STAGE_BYTES, Ahi,Alo,lda, Bhi,Blo,ldb,
                         bm,bn,N, k0+(i+2)*32, tid);
        CP_COMMIT();

        uint32_t base = sb + (i%3)*STAGE_BYTES;
#pragma unroll
        for (int ks=0; ks<2; ks++){
            const int kc = ks*2 + kc_l;
            uint32_t ah[2][4], al[2][4];
#pragma unroll
            for (int mf=0; mf<2; mf++){
                int row = wm*32 + mf*16 + a_row_l;
                uint32_t ad = base + (uint32_t)(row*64 + ((kc ^ ((row>>1)&3))<<4));
                LDSM4(ah[mf], ad);
                LDSM4(al[mf], ad + 8192);
            }
#pragma unroll
            for (int nf16=0; nf16<4; nf16++){
                int row = wn*64 + nf16*16 + a_row_l;
                uint32_t bd = base + 16384u + (uint32_t)(row*64 + ((kc ^ ((row>>1)&3))<<4));
                uint32_t bh[4], bl[4];
                LDSM4(bh, bd);
                LDSM4(bl, bd + 8192);
                const int n0 = nf16*2, n1 = nf16*2+1;
                // round 0: Ah*Bh  (4 independent MMAs)
                MMA(acc[0][n0], ah[0], bh[0], bh[2]);
                MMA(acc[0][n1], ah[0], bh[1], bh[3]);
                MMA(acc[1][n0], ah[1], bh[0], bh[2]);
                MMA(acc[1][n1], ah[1], bh[1], bh[3]);
                // round 1: Ah*Bl
                MMA(acc[0][n0], ah[0], bl[0], bl[2]);
                MMA(acc[0][n1], ah[0], bl[1], bl[3]);
                MMA(acc[1][n0], ah[1], bl[0], bl[2]);
                MMA(acc[1][n1], ah[1], bl[1], bl[3]);
                // round 2: Al*Bh
                MMA(acc[0][n0], al[0], bh[0], bh[2]);
                MMA(acc[0][n1], al[0], bh[1], bh[3]);
                MMA(acc[1][n0], al[1], bh[0], bh[2]);
                MMA(acc[1][n1], al[1], bh[1], bh[3]);
            }
        }
    }

    // epilogue
    float* Cz = C + (size_t)blockIdx.z*partStride;
    const bool even = ((ldc & 1) == 0);
#pragma unroll
    for (int mf=0; mf<2; mf++){
#pragma unroll
        for (int nf=0; nf<8; nf++){
            int rr = bm + wm*32 + mf*16 + (lane>>2);
            int cc = bn + wn*64 + nf*8 + ((lane&3)<<1);
#pragma unroll
            for (int h=0; h<2; h++){
                int r = rr + h*8;
                float v0 = acc[mf][nf][h*2+0];
                float v1 = acc[mf][nf][h*2+1];
                if (EPI==1){ v0 = softplus_f(v0+bias[cc]); v1 = softplus_f(v1+bias[cc+1]); }
                float* p = Cz + (size_t)r*ldc + cc;
                if (cc+1 < N){
                    if (even) *(float2*)p = make_float2(v0,v1);
                    else { p[0]=v0; p[1]=v1; }
                } else if (cc < N) p[0]=v0;
            }
        }
    }
}

// ===================== embedding gather =====================
__global__ void embed_k(const int* __restrict__ ids, const float* __restrict__ emb, float* __restrict__ res){
    int i = blockIdx.x*256 + threadIdx.x;
    int l = i >> 10;
    res[i] = emb[(size_t)ids[l]*DIM + (i & (DIM-1))];
}

// ===================== residual add (2 split-K partials) + RMSNorm -> hi/lo =====================
__global__ void addnorm_k(float* __restrict__ res, const float* __restrict__ p0,
                          const float* __restrict__ p1, const float* __restrict__ w,
                          bf* __restrict__ hhi, bf* __restrict__ hlo, int addX){
    int r = blockIdx.x;
    float* rr = res + (size_t)r*DIM;
    const float* q0 = p0 + (size_t)r*DIM;
    const float* q1 = p1 + (size_t)r*DIM;
    float v[4]; float s=0.f;
#pragma unroll
    for (int q=0;q<4;q++){
        int j = threadIdx.x + q*256;
        float val = rr[j];
        if (addX){ val += q0[j] + q1[j]; rr[j]=val; }
        v[q]=val; s += val*val;
    }
#pragma unroll
    for (int o=16;o>0;o>>=1) s += __shfl_xor_sync(0xffffffffu, s, o);
    __shared__ float red[8];
    if ((threadIdx.x&31)==0) red[threadIdx.x>>5]=s;
    __syncthreads();
    if (threadIdx.x<32){
        float t = (threadIdx.x<8)?red[threadIdx.x]:0.f;
#pragma unroll
        for (int o=4;o>0;o>>=1) t += __shfl_xor_sync(0xffffffffu,t,o);
        if (threadIdx.x==0) red[0] = rsqrtf(t/(float)DIM + 1e-5f);
    }
    __syncthreads();
    float inv = red[0];
#pragma unroll
    for (int q=0;q<4;q++){
        int j = threadIdx.x + q*256;
        float hv = v[q]*inv*w[j];
        size_t o = (size_t)r*DIM+j;
        split1(hv, hhi+o, hlo+o);
    }
}

// ===================== causal depthwise conv (K=4) + SiLU -> fp32 + hi/lo =====================
__global__ void conv_silu_k(const float* __restrict__ xz, const float* __restrict__ cw,
                            const float* __restrict__ cb, float* __restrict__ xc,
                            bf* __restrict__ xchi, bf* __restrict__ xclo){
    int i = blockIdx.x*256+threadIdx.x;   // i = l*EX + e
    int e = i & (EX-1);
    int l = i >> 11;
    float4 w = *(const float4*)(cw + e*4);
    const float* col = xz + e;
    float s = cb[e] + w.w*col[(size_t)l*(2*EX)];
    if (l>=1) s += w.z*col[(size_t)(l-1)*(2*EX)];
    if (l>=2) s += w.y*col[(size_t)(l-2)*(2*EX)];
    if (l>=3) s += w.x*col[(size_t)(l-3)*(2*EX)];
    float v = silu_f(s);
    xc[i] = v;
    split1(v, xchi+i, xclo+i);
}

// ===================== split-K reduction (x_proj) -> fp32 + hi/lo =====================
__global__ void reduceXP_k(const float* __restrict__ part, float* __restrict__ outp,
                           bf* __restrict__ dh, bf* __restrict__ dl){
    int i = blockIdx.x*256+threadIdx.x;
    float s=0.f;
#pragma unroll
    for (int z=0;z<XPS;z++) s += part[(size_t)z*SZ_DBC + i];
    outp[i]=s;
    split1(s, dh+i, dl+i);
}

// ===================== selective scan: chunked 3-phase =====================
__global__ __launch_bounds__(256)
void scanA_k(const float* __restrict__ dt, const float* __restrict__ xc, const float* __restrict__ dbc,
             const float* __restrict__ Alog, float* __restrict__ P, float* __restrict__ F){
    int e = blockIdx.x*256 + threadIdx.x;
    int c = blockIdx.y;
    __shared__ float Bsh[CHUNK][NS];
    for (int idx=threadIdx.x; idx<CHUNK*NS; idx+=256){
        int tt = idx>>4, n = idx&15;
        Bsh[tt][n] = dbc[(size_t)(c*CHUNK+tt)*XPN + DTRR + n];
    }
    __syncthreads();
    float Aa[NS], h[NS], p[NS];
#pragma unroll
    for (int n=0;n<NS;n++){ Aa[n] = -__expf(Alog[(size_t)e*NS+n]); h[n]=0.f; p[n]=1.f; }
    int t0=c*CHUNK;
    for (int tt=0;tt<CHUNK;tt++){
        int t=t0+tt;
        float dtv = dt[(size_t)t*EX+e];
        float du  = dtv*xc[(size_t)t*EX+e];
#pragma unroll
        for (int n=0;n<NS;n++){
            float dA = __expf(dtv*Aa[n]);
            h[n] = dA*h[n] + du*Bsh[tt][n];
            p[n]*= dA;
        }
    }
    size_t bse = ((size_t)c*EX + e)*NS;
#pragma unroll
    for (int n=0;n<NS;n++){ P[bse+n]=p[n]; F[bse+n]=h[n]; }
}

__global__ void scanB_k(const float* __restrict__ P, const float* __restrict__ F, float* __restrict__ Hin){
    int idx = blockIdx.x*256+threadIdx.x;
    float h=0.f;
    for (int c=0;c<NCH;c++){
        size_t o = (size_t)c*(EX*NS) + idx;
        Hin[o]=h;
        h = P[o]*h + F[o];
    }
}

__global__ __launch_bounds__(256)
void scanC_k(const float* __restrict__ dt, const float* __restrict__ xc, const float* __restrict__ dbc,
             const float* __restrict__ Alog, const float* __restrict__ Hin,
             const float* __restrict__ Dp, const float* __restrict__ xz,
             bf* __restrict__ yhi, bf* __restrict__ ylo){
    int e = blockIdx.x*256 + threadIdx.x;
    int c = blockIdx.y;
    __shared__ float Bsh[CHUNK][NS];
    __shared__ float Csh[CHUNK][NS];
    for (int idx=threadIdx.x; idx<CHUNK*NS; idx+=256){
        int tt = idx>>4, n = idx&15;
        const float* row = dbc + (size_t)(c*CHUNK+tt)*XPN;
        Bsh[tt][n] = row[DTRR+n];
        Csh[tt][n] = row[DTRR+NS+n];
    }
    __syncthreads();
    float Aa[NS], h[NS];
    size_t hb = ((size_t)c*EX+e)*NS;
#pragma unroll
    for (int n=0;n<NS;n++){ Aa[n]=-__expf(Alog[(size_t)e*NS+n]); h[n]=Hin[hb+n]; }
    float Dv = Dp[e];
    int t0=c*CHUNK;
    for (int tt=0;tt<CHUNK;tt++){
        int t=t0+tt;
        float dtv = dt[(size_t)t*EX+e];
        float xcv = xc[(size_t)t*EX+e];
        float du = dtv*xcv;
        float acc=0.f;
#pragma unroll
        for (int n=0;n<NS;n++){
            float dA=__expf(dtv*Aa[n]);
            h[n]=dA*h[n]+du*Bsh[tt][n];
            acc += h[n]*Csh[tt][n];
        }
        float z = xz[(size_t)t*(2*EX) + EX + e];
        float yv = (acc + Dv*xcv)*silu_f(z);
        size_t o = (size_t)t*EX+e;
        split1(yv, yhi+o, ylo+o);
    }
}

// ===================== orchestration =====================
extern "C" void kernel_launch(void* const* d_in, const int* in_sizes, int n_in,
                              void* d_out, int out_size) {
    const int*   ids  = (const int*)d_in[0];
    const float* emb  = (const float*)d_in[1];
    const float* inw  = (const float*)d_in[2];
    const float* cw   = (const float*)d_in[3];
    const float* cb   = (const float*)d_in[4];
    const float* xpw  = (const float*)d_in[5];
    const float* dtw  = (const float*)d_in[6];
    const float* dtb  = (const float*)d_in[7];
    const float* alog = (const float*)d_in[8];
    const float* dpar = (const float*)d_in[9];
    const float* outw = (const float*)d_in[10];
    const float* nw   = (const float*)d_in[11];
    const float* nfw  = (const float*)d_in[12];
    const float* hw   = (const float*)d_in[13];
    float* out = (float*)d_out;

    cudaFuncSetAttribute(mm_gemm<0>, cudaFuncAttributeMaxDynamicSharedMemorySize, MM_SMEM);
    cudaFuncSetAttribute(mm_gemm<1>, cudaFuncAttributeMaxDynamicSharedMemorySize, MM_SMEM);

    float* base = nullptr;
    cudaGetSymbolAddress((void**)&base, g_scr);
    float* p_res = base+O_RES; float* p_xp  = base+O_XP;  float* p_xz = base+O_XZ;
    float* p_xc  = base+O_XC;  float* p_dt  = base+O_DT;  float* p_dbc= base+O_DBC;
    float* p_P   = base+O_P;   float* p_F   = base+O_F;   float* p_hin= base+O_HIN;
    float* p_xpp = base+O_XPP;

    bf *inwh,*inwl,*xpwh,*xpwl,*dtwh,*dtwl,*outwh,*outwl,*hwh,*hwl;
    bf *hhi,*hlo,*xchi,*xclo,*dbch,*dbcl,*yhi,*ylo;
    cudaGetSymbolAddress((void**)&inwh, g_inwh);   cudaGetSymbolAddress((void**)&inwl, g_inwl);
    cudaGetSymbolAddress((void**)&xpwh, g_xpwh);   cudaGetSymbolAddress((void**)&xpwl, g_xpwl);
    cudaGetSymbolAddress((void**)&dtwh, g_dtwh);   cudaGetSymbolAddress((void**)&dtwl, g_dtwl);
    cudaGetSymbolAddress((void**)&outwh, g_outwh); cudaGetSymbolAddress((void**)&outwl, g_outwl);
    cudaGetSymbolAddress((void**)&hwh, g_hwh);     cudaGetSymbolAddress((void**)&hwl, g_hwl);
    cudaGetSymbolAddress((void**)&hhi, g_hhi);     cudaGetSymbolAddress((void**)&hlo, g_hlo);
    cudaGetSymbolAddress((void**)&xchi, g_xchi);   cudaGetSymbolAddress((void**)&xclo, g_xclo);
    cudaGetSymbolAddress((void**)&dbch, g_dbch);   cudaGetSymbolAddress((void**)&dbcl, g_dbcl);
    cudaGetSymbolAddress((void**)&yhi, g_yhi);     cudaGetSymbolAddress((void**)&ylo, g_ylo);

    // convert ALL weights once, in one launch
    cvtall_k<<<(int)((C_HW+255)/256),256>>>(inw, xpw, dtw, outw, hw);

    embed_k<<<(L*DIM)/256,256>>>(ids, emb, p_res);

    for (int i=0;i<NL;i++){
        // residual add of out_proj partials (skipped layer 0) + rmsnorm -> h (hi/lo)
        addnorm_k<<<L,256>>>(p_res, p_xp, p_xp+SZ_MAT, nw + (size_t)i*DIM, hhi, hlo, i>0);
        // xz = h @ in_proj^T   (2048 x 4096 x 1024)
        mm_gemm<0><<<dim3(L/128,(2*EX)/128,1),256,MM_SMEM>>>(hhi, hlo, DIM,
            inwh + (size_t)i*2*EX*DIM, inwl + (size_t)i*2*EX*DIM, DIM,
            p_xz, 2*EX, 0, 2*EX, DIM, nullptr);
        // causal depthwise conv + silu -> xc (fp32 + hi/lo)
        conv_silu_k<<<(L*EX)/256,256>>>(p_xz, cw + (size_t)i*EX*KC, cb + (size_t)i*EX,
                                        p_xc, xchi, xclo);
        // dbc = xc @ x_proj^T  (2048 x 96 x 2048), split-K x16 + reduce (+cvt)
        mm_gemm<0><<<dim3(L/128,1,XPS),256,MM_SMEM>>>(xchi, xclo, EX,
            xpwh + (size_t)i*XPN*EX, xpwl + (size_t)i*XPN*EX, EX,
            p_xpp, XPN, SZ_DBC, XPN, EX/XPS, nullptr);
        reduceXP_k<<<SZ_DBC/256,256>>>(p_xpp, p_dbc, dbch, dbcl);
        // dt = softplus(dbc[:, :64] @ dt_proj^T + dt_b)  (2048 x 2048 x 64)
        mm_gemm<1><<<dim3(L/128,EX/128,1),256,MM_SMEM>>>(dbch, dbcl, XPN,
            dtwh + (size_t)i*EX*DTRR, dtwl + (size_t)i*EX*DTRR, DTRR,
            p_dt, EX, 0, EX, DTRR, dtb + (size_t)i*EX);
        // chunked selective scan + z-gating -> y (hi/lo)
        scanA_k<<<dim3(EX/256,NCH),256>>>(p_dt, p_xc, p_dbc, alog + (size_t)i*EX*NS, p_P, p_F);
        scanB_k<<<(EX*NS)/256,256>>>(p_P, p_F, p_hin);
        scanC_k<<<dim3(EX/256,NCH),256>>>(p_dt, p_xc, p_dbc, alog + (size_t)i*EX*NS,
                                          p_hin, dpar + (size_t)i*EX, p_xz, yhi, ylo);
        // x = y @ out_proj^T   (2048 x 1024 x 2048), split-K x2 partials
        mm_gemm<0><<<dim3(L/128,DIM/128,OPS),256,MM_SMEM>>>(yhi, ylo, EX,
            outwh + (size_t)i*DIM*EX, outwl + (size_t)i*DIM*EX, EX,
            p_xp, DIM, SZ_MAT, DIM, EX/OPS, nullptr);
    }

    // final residual + rmsnorm, then LM head (2048 x 50257 x 1024)
    addnorm_k<<<L,256>>>(p_res, p_xp, p_xp+SZ_MAT, nfw, hhi, hlo, 1);
    mm_gemm<0><<<dim3(L/128,(VOCAB+127)/128,1),256,MM_SMEM>>>(hhi, hlo, DIM,
        hwh, hwl, DIM, out, VOCAB, 0, VOCAB, DIM, nullptr);
}

// round 17
// speedup vs baseline: 1.0269x; 1.0269x over previous
#include <cuda_runtime.h>
#include <cuda_bf16.h>
#include <math.h>
#include <cstdint>

#define L 2048
#define DIM 1024
#define NL 12
#define EX 2048
#define NS 16
#define DTRR 64
#define KC 4
#define VOCAB 50257
#define CHUNK 64
#define NCH 32
#define XPN 96
#define XPS 16         // split-K factor for x_proj
#define OPS 2          // split-K factor for out_proj

typedef __nv_bfloat16 bf;

__device__ __forceinline__ float silu_f(float x){ return x/(1.f+__expf(-x)); }
__device__ __forceinline__ float softplus_f(float x){ return fmaxf(x,0.f)+log1pf(__expf(-fabsf(x))); }

__device__ __forceinline__ void split1(float v, bf* hi, bf* lo){
    bf h = __float2bfloat16_rn(v);
    *hi = h;
    *lo = __float2bfloat16_rn(v - __bfloat162float(h));
}

__device__ __forceinline__ uint32_t smem_to_u32(const void* p){
    uint32_t a; asm("{ .reg .u64 t; cvta.to.shared.u64 t, %1; cvt.u32.u64 %0, t; }" : "=r"(a) : "l"(p));
    return a;
}
__device__ __forceinline__ void cp16(uint32_t dst, const void* src, int sz){
    asm volatile("cp.async.cg.shared.global [%0], [%1], 16, %2;" :: "r"(dst), "l"(src), "r"(sz));
}
#define CP_COMMIT() asm volatile("cp.async.commit_group;" ::: "memory")
#define CP_WAIT1()  asm volatile("cp.async.wait_group 1;" ::: "memory")

#define LDSM4(R, addr) \
  asm volatile("ldmatrix.sync.aligned.m8n8.x4.shared.b16 {%0,%1,%2,%3}, [%4];" \
    : "=r"((R)[0]),"=r"((R)[1]),"=r"((R)[2]),"=r"((R)[3]) : "r"(addr))

#define MMA(D, A, b0_, b1_) \
  asm volatile("mma.sync.aligned.m16n8k16.row.col.f32.bf16.bf16.f32 " \
    "{%0,%1,%2,%3}, {%4,%5,%6,%7}, {%8,%9}, {%0,%1,%2,%3};" \
    : "+f"((D)[0]),"+f"((D)[1]),"+f"((D)[2]),"+f"((D)[3]) \
    : "r"((A)[0]),"r"((A)[1]),"r"((A)[2]),"r"((A)[3]), "r"(b0_),"r"(b1_))

// ===================== scratch (static device memory) =====================
#define SZ_MAT (L*DIM)
#define SZ_XZ  (L*2*EX)
#define SZ_E   (L*EX)
#define SZ_DBC (L*XPN)
#define SZ_PF  (NCH*EX*NS)

#define O_RES 0
#define O_XP  (O_RES+SZ_MAT)            // out_proj partials: OPS x L x DIM
#define O_XZ  (O_XP+OPS*SZ_MAT)
#define O_XC  (O_XZ+SZ_XZ)
#define O_DT  (O_XC+SZ_E)
#define O_DBC (O_DT+SZ_E)
#define O_P   (O_DBC+SZ_DBC)
#define O_F   (O_P+SZ_PF)
#define O_HIN (O_F+SZ_PF)
#define O_XPP (O_HIN+SZ_PF)
#define SCRATCH_TOTAL (O_XPP + XPS*SZ_DBC)

__device__ __align__(256) float g_scr[SCRATCH_TOTAL];

// pre-converted hi/lo weight buffers (whole model, converted once per launch)
#define N_INW  (NL*2*EX*DIM)
#define N_XPW  (NL*XPN*EX)
#define N_DTW  (NL*EX*DTRR)
#define N_OUTW (NL*DIM*EX)
#define N_HW   (VOCAB*DIM)
__device__ __align__(256) bf g_inwh[N_INW],  g_inwl[N_INW];
__device__ __align__(256) bf g_xpwh[N_XPW],  g_xpwl[N_XPW];
__device__ __align__(256) bf g_dtwh[N_DTW],  g_dtwl[N_DTW];
__device__ __align__(256) bf g_outwh[N_OUTW],g_outwl[N_OUTW];
__device__ __align__(256) bf g_hwh[N_HW],    g_hwl[N_HW];
// activation hi/lo buffers
__device__ __align__(256) bf g_hhi[L*DIM],  g_hlo[L*DIM];
__device__ __align__(256) bf g_xchi[L*EX],  g_xclo[L*EX];
__device__ __align__(256) bf g_dbch[L*XPN], g_dbcl[L*XPN];
__device__ __align__(256) bf g_yhi[L*EX],   g_ylo[L*EX];

// ===================== all-weights fp32 -> (hi,lo) split, one kernel =====================
#define C_INW  (N_INW/8)
#define C_XPW  (C_INW + N_XPW/8)
#define C_DTW  (C_XPW + N_DTW/8)
#define C_OUTW (C_DTW + N_OUTW/8)
#define C_HW   (C_OUTW + N_HW/8)

__device__ __forceinline__ void cvt8_one(const float* __restrict__ src, bf* hi, bf* lo, size_t i){
    const float4* s = (const float4*)src + 2*i;
    float4 a = s[0], b = s[1];
    float f[8] = {a.x,a.y,a.z,a.w,b.x,b.y,b.z,b.w};
    union { bf h[8]; uint4 u; } H; union { bf l[8]; uint4 u; } Lo;
#pragma unroll
    for (int j=0;j<8;j++) split1(f[j], &H.h[j], &Lo.l[j]);
    ((uint4*)hi)[i] = H.u;
    ((uint4*)lo)[i] = Lo.u;
}

__global__ void cvtall_k(const float* __restrict__ inw, const float* __restrict__ xpw,
                         const float* __restrict__ dtw, const float* __restrict__ outw,
                         const float* __restrict__ hw){
    size_t i = (size_t)blockIdx.x*256 + threadIdx.x;
    if (i < C_INW)       cvt8_one(inw,  g_inwh,  g_inwl,  i);
    else if (i < C_XPW)  cvt8_one(xpw,  g_xpwh,  g_xpwl,  i - C_INW);
    else if (i < C_DTW)  cvt8_one(dtw,  g_dtwh,  g_dtwl,  i - C_XPW);
    else if (i < C_OUTW) cvt8_one(outw, g_outwh, g_outwl, i - C_DTW);
    else if (i < C_HW)   cvt8_one(hw,   g_hwh,   g_hwl,   i - C_OUTW);
}

// ===================== mma.sync bf16x3 GEMM: C[M,N] = A[M,K] * B[N,K]^T =====================
// 128x128 CTA tile, BK=32, 3-stage cp.async pipeline, 8 warps (4m x 2n),
// warp tile 32x64. bf16x3: acc += Ah*Bh + Ah*Bl + Al*Bh.
// Instruction-minimal mainloop: all swizzled addresses are stage_base + const
// (swizzle invariant under 16-row steps; ks step is addr^32); ldgsts sources
// are running pointers; B fragments double-buffered across the nf16 loop.
#define STAGE_BYTES 32768
#define MM_SMEM (3*STAGE_BYTES)

#define LDG8(dsb) do{ \
    cp16((dsb),         pAh,      16); cp16((dsb)+4096,  pAh+a2, 16); \
    cp16((dsb)+8192,    pAl,      16); cp16((dsb)+12288, pAl+a2, 16); \
    cp16((dsb)+16384,   pBh0,    ok0); cp16((dsb)+20480, pBh1,  ok1); \
    cp16((dsb)+24576,   pBl0,    ok0); cp16((dsb)+28672, pBl1,  ok1); }while(0)
#define ADV() do{ pAh+=32; pAl+=32; pBh0+=32; pBh1+=32; pBl0+=32; pBl1+=32; }while(0)

template<int EPI>
__global__ __launch_bounds__(256,2)
void mm_gemm(const bf* __restrict__ Ahi, const bf* __restrict__ Alo, int lda,
             const bf* __restrict__ Bhi, const bf* __restrict__ Blo, int ldb,
             float* __restrict__ C, int ldc, int partStride, int N, int kLen,
             const float* __restrict__ bias)
{
    extern __shared__ char smem[];
    const uint32_t sb = smem_to_u32(smem);
    const int tid = threadIdx.x, lane = tid&31, wid = tid>>5;
    const int wm = wid&3, wn = wid>>2;
    const int bm = blockIdx.x*128, bn = blockIdx.y*128;
    const int k0 = blockIdx.z*kLen;
    const int ktiles = kLen/32;

    // ---- ldgsts setup: per-thread row/col, all loop-invariant ----
    const int lrow = tid>>2, lkc = tid&3;
    const uint32_t d0 = (uint32_t)(lrow*64 + ((lkc ^ ((lrow>>1)&3))<<4));
    const size_t a2 = (size_t)64*lda;
    const int br0 = bn+lrow, br1 = bn+lrow+64;
    const int ok0 = (br0<N)?16:0, ok1 = (br1<N)?16:0;
    const bf* pAh = Ahi + (size_t)(bm+lrow)*lda + k0 + lkc*8;
    const bf* pAl = Alo + (size_t)(bm+lrow)*lda + k0 + lkc*8;
    const bf* pBh0 = Bhi + (size_t)(ok0?br0:bn)*ldb + k0 + lkc*8;
    const bf* pBl0 = Blo + (size_t)(ok0?br0:bn)*ldb + k0 + lkc*8;
    const bf* pBh1 = Bhi + (size_t)(ok1?br1:bn)*ldb + k0 + lkc*8;
    const bf* pBl1 = Blo + (size_t)(ok1?br1:bn)*ldb + k0 + lkc*8;

    // prologue: stages 0,1
    LDG8(sb + d0); ADV(); CP_COMMIT();
    LDG8(sb + STAGE_BYTES + d0); ADV(); CP_COMMIT();

    // ---- fragment addresses: stage_base + const, ks toggles ^32 ----
    const int r15 = lane&15;
    const uint32_t swz = (uint32_t)((r15>>1)&3);
    const uint32_t colx = (uint32_t)(((lane>>4) ^ swz)<<4);
    const uint32_t aL0 = (uint32_t)((wm*32+r15)*64) + colx;
    const uint32_t bL0 = 16384u + (uint32_t)((wn*64+r15)*64) + colx;
    const uint32_t aL1 = aL0 ^ 32u, bL1 = bL0 ^ 32u;

    float acc[2][8][4];
#pragma unroll
    for (int a=0;a<2;a++)
#pragma unroll
        for (int b=0;b<8;b++)
#pragma unroll
            for (int c=0;c<4;c++) acc[a][b][c]=0.f;

    uint32_t stb = sb;                                  // compute stage base
    uint32_t pds = sb + 2*STAGE_BYTES + d0;             // prefetch dst
    const uint32_t wrapS = sb + 3*STAGE_BYTES;
    const uint32_t wrapP = sb + 3*STAGE_BYTES + d0;

    for (int i=0;i<ktiles;i++){
        CP_WAIT1();
        __syncthreads();
        if (i+2 < ktiles){ LDG8(pds); ADV(); }
        CP_COMMIT();
        pds += STAGE_BYTES; if (pds == wrapP) pds = sb + d0;

#pragma unroll
        for (int ks=0; ks<2; ks++){
            const uint32_t ab = stb + (ks ? aL1 : aL0);
            const uint32_t bb = stb + (ks ? bL1 : bL0);
            uint32_t ah[2][4], al[2][4];
            LDSM4(ah[0], ab);        LDSM4(ah[1], ab+1024);
            LDSM4(al[0], ab+8192);   LDSM4(al[1], ab+9216);
            uint32_t bh[2][4], bl[2][4];
            LDSM4(bh[0], bb);        LDSM4(bl[0], bb+8192);
#pragma unroll
            for (int nf16=0; nf16<4; nf16++){
                const int cur = nf16&1, nxt = cur^1;
                if (nf16<3){
                    LDSM4(bh[nxt], bb+(nf16+1)*1024);
                    LDSM4(bl[nxt], bb+(nf16+1)*1024+8192);
                }
                const int n0 = nf16*2, n1 = n0+1;
                MMA(acc[0][n0], ah[0], bh[cur][0], bh[cur][2]);
                MMA(acc[0][n1], ah[0], bh[cur][1], bh[cur][3]);
                MMA(acc[1][n0], ah[1], bh[cur][0], bh[cur][2]);
                MMA(acc[1][n1], ah[1], bh[cur][1], bh[cur][3]);
                MMA(acc[0][n0], ah[0], bl[cur][0], bl[cur][2]);
                MMA(acc[0][n1], ah[0], bl[cur][1], bl[cur][3]);
                MMA(acc[1][n0], ah[1], bl[cur][0], bl[cur][2]);
                MMA(acc[1][n1], ah[1], bl[cur][1], bl[cur][3]);
                MMA(acc[0][n0], al[0], bh[cur][0], bh[cur][2]);
                MMA(acc[0][n1], al[0], bh[cur][1], bh[cur][3]);
                MMA(acc[1][n0], al[1], bh[cur][0], bh[cur][2]);
                MMA(acc[1][n1], al[1], bh[cur][1], bh[cur][3]);
            }
        }
        stb += STAGE_BYTES; if (stb == wrapS) stb = sb;
    }

    // epilogue
    float* Cz = C + (size_t)blockIdx.z*partStride;
    const bool even = ((ldc & 1) == 0);
#pragma unroll
    for (int mf=0; mf<2; mf++){
#pragma unroll
        for (int nf=0; nf<8; nf++){
            int rr = bm + wm*32 + mf*16 + (lane>>2);
            int cc = bn + wn*64 + nf*8 + ((lane&3)<<1);
#pragma unroll
            for (int h=0; h<2; h++){
                int r = rr + h*8;
                float v0 = acc[mf][nf][h*2+0];
                float v1 = acc[mf][nf][h*2+1];
                if (EPI==1){ v0 = softplus_f(v0+bias[cc]); v1 = softplus_f(v1+bias[cc+1]); }
                float* p = Cz + (size_t)r*ldc + cc;
                if (cc+1 < N){
                    if (even) *(float2*)p = make_float2(v0,v1);
                    else { p[0]=v0; p[1]=v1; }
                } else if (cc < N) p[0]=v0;
            }
        }
    }
}

// ===================== embedding gather =====================
__global__ void embed_k(const int* __restrict__ ids, const float* __restrict__ emb, float* __restrict__ res){
    int i = blockIdx.x*256 + threadIdx.x;
    int l = i >> 10;
    res[i] = emb[(size_t)ids[l]*DIM + (i & (DIM-1))];
}

// ===================== residual add (2 split-K partials) + RMSNorm -> hi/lo =====================
__global__ void addnorm_k(float* __restrict__ res, const float* __restrict__ p0,
                          const float* __restrict__ p1, const float* __restrict__ w,
                          bf* __restrict__ hhi, bf* __restrict__ hlo, int addX){
    int r = blockIdx.x;
    float* rr = res + (size_t)r*DIM;
    const float* q0 = p0 + (size_t)r*DIM;
    const float* q1 = p1 + (size_t)r*DIM;
    float v[4]; float s=0.f;
#pragma unroll
    for (int q=0;q<4;q++){
        int j = threadIdx.x + q*256;
        float val = rr[j];
        if (addX){ val += q0[j] + q1[j]; rr[j]=val; }
        v[q]=val; s += val*val;
    }
#pragma unroll
    for (int o=16;o>0;o>>=1) s += __shfl_xor_sync(0xffffffffu, s, o);
    __shared__ float red[8];
    if ((threadIdx.x&31)==0) red[threadIdx.x>>5]=s;
    __syncthreads();
    if (threadIdx.x<32){
        float t = (threadIdx.x<8)?red[threadIdx.x]:0.f;
#pragma unroll
        for (int o=4;o>0;o>>=1) t += __shfl_xor_sync(0xffffffffu,t,o);
        if (threadIdx.x==0) red[0] = rsqrtf(t/(float)DIM + 1e-5f);
    }
    __syncthreads();
    float inv = red[0];
#pragma unroll
    for (int q=0;q<4;q++){
        int j = threadIdx.x + q*256;
        float hv = v[q]*inv*w[j];
        size_t o = (size_t)r*DIM+j;
        split1(hv, hhi+o, hlo+o);
    }
}

// ===================== causal depthwise conv (K=4) + SiLU -> fp32 + hi/lo =====================
__global__ void conv_silu_k(const float* __restrict__ xz, const float* __restrict__ cw,
                            const float* __restrict__ cb, float* __restrict__ xc,
                            bf* __restrict__ xchi, bf* __restrict__ xclo){
    int i = blockIdx.x*256+threadIdx.x;   // i = l*EX + e
    int e = i & (EX-1);
    int l = i >> 11;
    float4 w = *(const float4*)(cw + e*4);
    const float* col = xz + e;
    float s = cb[e] + w.w*col[(size_t)l*(2*EX)];
    if (l>=1) s += w.z*col[(size_t)(l-1)*(2*EX)];
    if (l>=2) s += w.y*col[(size_t)(l-2)*(2*EX)];
    if (l>=3) s += w.x*col[(size_t)(l-3)*(2*EX)];
    float v = silu_f(s);
    xc[i] = v;
    split1(v, xchi+i, xclo+i);
}

// ===================== split-K reduction (x_proj) -> fp32 + hi/lo =====================
__global__ void reduceXP_k(const float* __restrict__ part, float* __restrict__ outp,
                           bf* __restrict__ dh, bf* __restrict__ dl){
    int i = blockIdx.x*256+threadIdx.x;
    float s=0.f;
#pragma unroll
    for (int z=0;z<XPS;z++) s += part[(size_t)z*SZ_DBC + i];
    outp[i]=s;
    split1(s, dh+i, dl+i);
}

// ===================== selective scan: chunked 3-phase =====================
__global__ __launch_bounds__(256)
void scanA_k(const float* __restrict__ dt, const float* __restrict__ xc, const float* __restrict__ dbc,
             const float* __restrict__ Alog, float* __restrict__ P, float* __restrict__ F){
    int e = blockIdx.x*256 + threadIdx.x;
    int c = blockIdx.y;
    __shared__ float Bsh[CHUNK][NS];
    for (int idx=threadIdx.x; idx<CHUNK*NS; idx+=256){
        int tt = idx>>4, n = idx&15;
        Bsh[tt][n] = dbc[(size_t)(c*CHUNK+tt)*XPN + DTRR + n];
    }
    __syncthreads();
    float Aa[NS], h[NS], p[NS];
#pragma unroll
    for (int n=0;n<NS;n++){ Aa[n] = -__expf(Alog[(size_t)e*NS+n]); h[n]=0.f; p[n]=1.f; }
    int t0=c*CHUNK;
    for (int tt=0;tt<CHUNK;tt++){
        int t=t0+tt;
        float dtv = dt[(size_t)t*EX+e];
        float du  = dtv*xc[(size_t)t*EX+e];
#pragma unroll
        for (int n=0;n<NS;n++){
            float dA = __expf(dtv*Aa[n]);
            h[n] = dA*h[n] + du*Bsh[tt][n];
            p[n]*= dA;
        }
    }
    size_t bse = ((size_t)c*EX + e)*NS;
#pragma unroll
    for (int n=0;n<NS;n++){ P[bse+n]=p[n]; F[bse+n]=h[n]; }
}

__global__ void scanB_k(const float* __restrict__ P, const float* __restrict__ F, float* __restrict__ Hin){
    int idx = blockIdx.x*256+threadIdx.x;
    float h=0.f;
    for (int c=0;c<NCH;c++){
        size_t o = (size_t)c*(EX*NS) + idx;
        Hin[o]=h;
        h = P[o]*h + F[o];
    }
}

__global__ __launch_bounds__(256)
void scanC_k(const float* __restrict__ dt, const float* __restrict__ xc, const float* __restrict__ dbc,
             const float* __restrict__ Alog, const float* __restrict__ Hin,
             const float* __restrict__ Dp, const float* __restrict__ xz,
             bf* __restrict__ yhi, bf* __restrict__ ylo){
    int e = blockIdx.x*256 + threadIdx.x;
    int c = blockIdx.y;
    __shared__ float Bsh[CHUNK][NS];
    __shared__ float Csh[CHUNK][NS];
    for (int idx=threadIdx.x; idx<CHUNK*NS; idx+=256){
        int tt = idx>>4, n = idx&15;
        const float* row = dbc + (size_t)(c*CHUNK+tt)*XPN;
        Bsh[tt][n] = row[DTRR+n];
        Csh[tt][n] = row[DTRR+NS+n];
    }
    __syncthreads();
    float Aa[NS], h[NS];
    size_t hb = ((size_t)c*EX+e)*NS;
#pragma unroll
    for (int n=0;n<NS;n++){ Aa[n]=-__expf(Alog[(size_t)e*NS+n]); h[n]=Hin[hb+n]; }
    float Dv = Dp[e];
    int t0=c*CHUNK;
    for (int tt=0;tt<CHUNK;tt++){
        int t=t0+tt;
        float dtv = dt[(size_t)t*EX+e];
        float xcv = xc[(size_t)t*EX+e];
        float du = dtv*xcv;
        float acc=0.f;
#pragma unroll
        for (int n=0;n<NS;n++){
            float dA=__expf(dtv*Aa[n]);
            h[n]=dA*h[n]+du*Bsh[tt][n];
            acc += h[n]*Csh[tt][n];
        }
        float z = xz[(size_t)t*(2*EX) + EX + e];
        float yv = (acc + Dv*xcv)*silu_f(z);
        size_t o = (size_t)t*EX+e;
        split1(yv, yhi+o, ylo+o);
    }
}

// ===================== orchestration =====================
extern "C" void kernel_launch(void* const* d_in, const int* in_sizes, int n_in,
                              void* d_out, int out_size) {
    const int*   ids  = (const int*)d_in[0];
    const float* emb  = (const float*)d_in[1];
    const float* inw  = (const float*)d_in[2];
    const float* cw   = (const float*)d_in[3];
    const float* cb   = (const float*)d_in[4];
    const float* xpw  = (const float*)d_in[5];
    const float* dtw  = (const float*)d_in[6];
    const float* dtb  = (const float*)d_in[7];
    const float* alog = (const float*)d_in[8];
    const float* dpar = (const float*)d_in[9];
    const float* outw = (const float*)d_in[10];
    const float* nw   = (const float*)d_in[11];
    const float* nfw  = (const float*)d_in[12];
    const float* hw   = (const float*)d_in[13];
    float* out = (float*)d_out;

    cudaFuncSetAttribute(mm_gemm<0>, cudaFuncAttributeMaxDynamicSharedMemorySize, MM_SMEM);
    cudaFuncSetAttribute(mm_gemm<1>, cudaFuncAttributeMaxDynamicSharedMemorySize, MM_SMEM);

    float* base = nullptr;
    cudaGetSymbolAddress((void**)&base, g_scr);
    float* p_res = base+O_RES; float* p_xp  = base+O_XP;  float* p_xz = base+O_XZ;
    float* p_xc  = base+O_XC;  float* p_dt  = base+O_DT;  float* p_dbc= base+O_DBC;
    float* p_P   = base+O_P;   float* p_F   = base+O_F;   float* p_hin= base+O_HIN;
    float* p_xpp = base+O_XPP;

    bf *inwh,*inwl,*xpwh,*xpwl,*dtwh,*dtwl,*outwh,*outwl,*hwh,*hwl;
    bf *hhi,*hlo,*xchi,*xclo,*dbch,*dbcl,*yhi,*ylo;
    cudaGetSymbolAddress((void**)&inwh, g_inwh);   cudaGetSymbolAddress((void**)&inwl, g_inwl);
    cudaGetSymbolAddress((void**)&xpwh, g_xpwh);   cudaGetSymbolAddress((void**)&xpwl, g_xpwl);
    cudaGetSymbolAddress((void**)&dtwh, g_dtwh);   cudaGetSymbolAddress((void**)&dtwl, g_dtwl);
    cudaGetSymbolAddress((void**)&outwh, g_outwh); cudaGetSymbolAddress((void**)&outwl, g_outwl);
    cudaGetSymbolAddress((void**)&hwh, g_hwh);     cudaGetSymbolAddress((void**)&hwl, g_hwl);
    cudaGetSymbolAddress((void**)&hhi, g_hhi);     cudaGetSymbolAddress((void**)&hlo, g_hlo);
    cudaGetSymbolAddress((void**)&xchi, g_xchi);   cudaGetSymbolAddress((void**)&xclo, g_xclo);
    cudaGetSymbolAddress((void**)&dbch, g_dbch);   cudaGetSymbolAddress((void**)&dbcl, g_dbcl);
    cudaGetSymbolAddress((void**)&yhi, g_yhi);     cudaGetSymbolAddress((void**)&ylo, g_ylo);

    // convert ALL weights once, in one launch
    cvtall_k<<<(int)((C_HW+255)/256),256>>>(inw, xpw, dtw, outw, hw);

    embed_k<<<(L*DIM)/256,256>>>(ids, emb, p_res);

    for (int i=0;i<NL;i++){
        // residual add of out_proj partials (skipped layer 0) + rmsnorm -> h (hi/lo)
        addnorm_k<<<L,256>>>(p_res, p_xp, p_xp+SZ_MAT, nw + (size_t)i*DIM, hhi, hlo, i>0);
        // xz = h @ in_proj^T   (2048 x 4096 x 1024)
        mm_gemm<0><<<dim3(L/128,(2*EX)/128,1),256,MM_SMEM>>>(hhi, hlo, DIM,
            inwh + (size_t)i*2*EX*DIM, inwl + (size_t)i*2*EX*DIM, DIM,
            p_xz, 2*EX, 0, 2*EX, DIM, nullptr);
        // causal depthwise conv + silu -> xc (fp32 + hi/lo)
        conv_silu_k<<<(L*EX)/256,256>>>(p_xz, cw + (size_t)i*EX*KC, cb + (size_t)i*EX,
                                        p_xc, xchi, xclo);
        // dbc = xc @ x_proj^T  (2048 x 96 x 2048), split-K x16 + reduce (+cvt)
        mm_gemm<0><<<dim3(L/128,1,XPS),256,MM_SMEM>>>(xchi, xclo, EX,
            xpwh + (size_t)i*XPN*EX, xpwl + (size_t)i*XPN*EX, EX,
            p_xpp, XPN, SZ_DBC, XPN, EX/XPS, nullptr);
        reduceXP_k<<<SZ_DBC/256,256>>>(p_xpp, p_dbc, dbch, dbcl);
        // dt = softplus(dbc[:, :64] @ dt_proj^T + dt_b)  (2048 x 2048 x 64)
        mm_gemm<1><<<dim3(L/128,EX/128,1),256,MM_SMEM>>>(dbch, dbcl, XPN,
            dtwh + (size_t)i*EX*DTRR, dtwl + (size_t)i*EX*DTRR, DTRR,
            p_dt, EX, 0, EX, DTRR, dtb + (size_t)i*EX);
        // chunked selective scan + z-gating -> y (hi/lo)
        scanA_k<<<dim3(EX/256,NCH),256>>>(p_dt, p_xc, p_dbc, alog + (size_t)i*EX*NS, p_P, p_F);
        scanB_k<<<(EX*NS)/256,256>>>(p_P, p_F, p_hin);
        scanC_k<<<dim3(EX/256,NCH),256>>>(p_dt, p_xc, p_dbc, alog + (size_t)i*EX*NS,
                                          p_hin, dpar + (size_t)i*EX, p_xz, yhi, ylo);
        // x = y @ out_proj^T   (2048 x 1024 x 2048), split-K x2 partials
        mm_gemm<0><<<dim3(L/128,DIM/128,OPS),256,MM_SMEM>>>(yhi, ylo, EX,
            outwh + (size_t)i*DIM*EX, outwl + (size_t)i*DIM*EX, EX,
            p_xp, DIM, SZ_MAT, DIM, EX/OPS, nullptr);
    }

    // final residual + rmsnorm, then LM head (2048 x 50257 x 1024)
    addnorm_k<<<L,256>>>(p_res, p_xp, p_xp+SZ_MAT, nfw, hhi, hlo, 1);
    mm_gemm<0><<<dim3(L/128,(VOCAB+127)/128,1),256,MM_SMEM>>>(hhi, hlo, DIM,
        hwh, hwl, DIM, out, VOCAB, 0, VOCAB, DIM, nullptr);
}